// round 9
// baseline (speedup 1.0000x reference)
#include <cuda_runtime.h>
#include <cuda_fp16.h>
#include <math.h>
#include <stdint.h>

#define B_ 32
#define T_ 1024
#define D_ 512
#define H_ 2048
#define E_ 8

#define BM 128
#define BN 128
#define BK 64                    // halves per k-tile (4 x k16 mma steps), 128B rows
#define STAGES 3

#define A_BYTES (BM * 128)                    // 16384
#define B_BYTES (BN * 128)                    // 16384
#define STAGE_BYTES (A_BYTES + B_BYTES)       // 32768
#define SMEMSZ (STAGES * STAGE_BYTES)         // 98304

// mega-kernel bid layout
#define NB_W1   2048
#define NB_POOL 256
#define NB_W2   2048
#define NB_G1   4096                          // paired m-tiles: 16 xt * 4 ypair * 64 bz
#define NB_G2   1024
#define OFF_POOL (NB_W1)
#define OFF_W2   (NB_W1 + NB_POOL)
#define OFF_G1   (OFF_W2 + NB_W2)
#define OFF_G2   (OFF_G1 + NB_G1)
#define NB_ALL   (OFF_G2 + NB_G2)

// ---------------------------------------------------------------------------
// scratch (device globals — no allocation allowed)
// ---------------------------------------------------------------------------
__device__ int      g_eidx[B_][2];
__device__ float    g_prob[B_][2];
__device__ float    g_pool[B_][8][D_];
__device__ unsigned g_w1c[E_ * 16];                  // w1t slice readiness (target 16)
__device__ unsigned g_w2c[E_ * 4];                   // w2t slice readiness (target 64)
__device__ unsigned g_poolc[B_];                     // pool blocks done per batch (8)
__device__ unsigned g_gatef[B_];                     // gate ready flag
__device__ unsigned g_cnt[B_][8];                    // gemm1->gemm2 readiness (32)
__device__ __half   g_xh[(size_t)B_ * T_ * D_];      // fp16 x
__device__ __half   g_w1t[(size_t)E_ * H_ * D_];     // w1^T [E][H][D] fp16
__device__ __half   g_w2t[(size_t)E_ * D_ * H_];     // w2^T [E][D][H] fp16
__device__ __half   g_h[(size_t)B_ * T_ * (2 * H_)]; // p*silu(x@w1+b1) fp16

// ---------------------------------------------------------------------------
// helpers
// ---------------------------------------------------------------------------
__device__ __forceinline__ uint32_t smem_u32(const void* p) {
    uint32_t a;
    asm("{ .reg .u64 t; cvta.to.shared.u64 t, %1; cvt.u32.u64 %0, t; }" : "=r"(a) : "l"(p));
    return a;
}
__device__ __forceinline__ void cp16(uint32_t dst, const void* src) {
    asm volatile("cp.async.cg.shared.global [%0], [%1], 16;" :: "r"(dst), "l"(src));
}
__device__ __forceinline__ void cp_commit() {
    asm volatile("cp.async.commit_group;" ::: "memory");
}
template <int N>
__device__ __forceinline__ void cp_wait() {
    asm volatile("cp.async.wait_group %0;" :: "n"(N) : "memory");
}
__device__ __forceinline__ void ldsm_x4(unsigned& r0, unsigned& r1, unsigned& r2,
                                        unsigned& r3, uint32_t addr) {
    asm volatile("ldmatrix.sync.aligned.m8n8.x4.shared.b16 {%0,%1,%2,%3}, [%4];"
        : "=r"(r0), "=r"(r1), "=r"(r2), "=r"(r3) : "r"(addr));
}
__device__ __forceinline__ void ldsm_x2(unsigned& r0, unsigned& r1, uint32_t addr) {
    asm volatile("ldmatrix.sync.aligned.m8n8.x2.shared.b16 {%0,%1}, [%2];"
        : "=r"(r0), "=r"(r1) : "r"(addr));
}
__device__ __forceinline__ void mma_f16(float* d, const unsigned* a, const unsigned* b) {
    asm volatile(
        "mma.sync.aligned.m16n8k16.row.col.f32.f16.f16.f32 "
        "{%0,%1,%2,%3}, {%4,%5,%6,%7}, {%8,%9}, {%0,%1,%2,%3};\n"
        : "+f"(d[0]), "+f"(d[1]), "+f"(d[2]), "+f"(d[3])
        : "r"(a[0]), "r"(a[1]), "r"(a[2]), "r"(a[3]), "r"(b[0]), "r"(b[1]));
}
__device__ __forceinline__ void spin_ge(const unsigned* p, unsigned target) {
    unsigned v;
    do {
        asm volatile("ld.global.acquire.gpu.u32 %0, [%1];" : "=r"(v) : "l"(p) : "memory");
        if (v < target) __nanosleep(128);
    } while (v < target);
}

// ---------------------------------------------------------------------------
// reset kernel (runs first each call; kernel boundary orders it before mega)
// ---------------------------------------------------------------------------
__global__ void reset_kernel() {
    const int i = threadIdx.x;   // 512 threads
    if (i < E_ * 16) g_w1c[i] = 0u;
    if (i < E_ * 4)  g_w2c[i] = 0u;
    if (i < B_)      { g_poolc[i] = 0u; g_gatef[i] = 0u; }
    if (i < B_ * 8)  ((unsigned*)g_cnt)[i] = 0u;
}

// ---------------------------------------------------------------------------
// 64x64 transpose tile (256 threads), float src -> half dst (transposed)
// ---------------------------------------------------------------------------
__device__ __forceinline__ void transpose64(const float* __restrict__ S,
                                            __half* __restrict__ Dp,
                                            int R, int C, int r0, int c0,
                                            float (*tile)[65], int tid) {
    const int tx = tid & 63, ty = tid >> 6;     // ty 0..3
    #pragma unroll
    for (int i = 0; i < 16; i++) {
        const int row = ty + i * 4;
        tile[row][tx] = S[(size_t)(r0 + row) * C + c0 + tx];
    }
    __syncthreads();
    #pragma unroll
    for (int i = 0; i < 16; i++) {
        const int row = ty + i * 4;
        Dp[(size_t)(c0 + row) * R + r0 + tx] = __float2half_rn(tile[tx][row]);
    }
}

// ---------------------------------------------------------------------------
// GEMM core macros: 256 threads, 8 warps 2(m)x4(n), warp tile 64x32
// Tiles: 128 rows x 128B, XOR-swizzled: chunk_phys = chunk ^ (row&7)
// ---------------------------------------------------------------------------
#define ISSUE_STAGE(slot, A_SRC, B_SRC) do {                                   \
    const uint32_t _as = sm_base + (slot) * STAGE_BYTES;                       \
    const uint32_t _bs = _as + A_BYTES;                                        \
    _Pragma("unroll")                                                          \
    for (int _i = 0; _i < 4; _i++) {                                           \
        const int _c = _i * 256 + tid;                                         \
        const int _r = _c >> 3, _lc = _c & 7;                                  \
        cp16(_as + _r * 128 + ((_lc ^ (_r & 7)) << 4), (A_SRC(_r, _lc)));      \
    }                                                                          \
    _Pragma("unroll")                                                          \
    for (int _i = 0; _i < 4; _i++) {                                           \
        const int _c = _i * 256 + tid;                                         \
        const int _r = _c >> 3, _lc = _c & 7;                                  \
        cp16(_bs + _r * 128 + ((_lc ^ (_r & 7)) << 4), (B_SRC(_r, _lc)));      \
    }                                                                          \
} while (0)

#define COMPUTE_STAGE(slot) do {                                               \
    const uint32_t _ab = sm_base + (slot) * STAGE_BYTES;                       \
    const uint32_t _bb = _ab + A_BYTES;                                        \
    _Pragma("unroll")                                                          \
    for (int ks = 0; ks < 4; ks++) {                                           \
        unsigned af[4][4], bf[4][2];                                           \
        _Pragma("unroll")                                                      \
        for (int mt = 0; mt < 4; mt++)                                         \
            ldsm_x4(af[mt][0], af[mt][1], af[mt][2], af[mt][3],                \
                    _ab + arow_off + mt * 2048 + (((2 * ks + ac) ^ sxor) << 4)); \
        _Pragma("unroll")                                                      \
        for (int nt = 0; nt < 4; nt++)                                         \
            ldsm_x2(bf[nt][0], bf[nt][1],                                      \
                    _bb + brow_off + nt * 1024 + (((2 * ks + bc) ^ sxor) << 4)); \
        _Pragma("unroll")                                                      \
        for (int mt = 0; mt < 4; mt++)                                         \
            _Pragma("unroll")                                                  \
            for (int nt = 0; nt < 4; nt++)                                     \
                mma_f16(acc[mt][nt], af[mt], bf[nt]);                          \
    }                                                                          \
} while (0)

#define GEMM_PIPELINE(NK, A_SRC, B_SRC) do {                                   \
    _Pragma("unroll")                                                          \
    for (int s = 0; s < STAGES - 1; s++) {                                     \
        const int kk = s;                                                      \
        ISSUE_STAGE(s, A_SRC, B_SRC);                                          \
        cp_commit();                                                           \
    }                                                                          \
    for (int kt = 0; kt < (NK); kt++) {                                        \
        cp_wait<STAGES - 2>();                                                 \
        __syncthreads();                                                       \
        const int pf = kt + STAGES - 1;                                        \
        if (pf < (NK)) {                                                       \
            const int kk = pf;                                                 \
            ISSUE_STAGE(pf % STAGES, A_SRC, B_SRC);                            \
        }                                                                      \
        cp_commit();                                                           \
        COMPUTE_STAGE(kt % STAGES);                                            \
    }                                                                          \
} while (0)

#define LANE_OFFS()                                                            \
    const int wm = (warp & 1) * 64;                                            \
    const int wn = (warp >> 1) * 32;                                           \
    const uint32_t arow_off = (uint32_t)(wm + (lane & 15)) * 128;              \
    const uint32_t ac = (uint32_t)(lane >> 4);                                 \
    const uint32_t brow_off = (uint32_t)(wn + (lane & 7)) * 128;               \
    const uint32_t bc = (uint32_t)((lane >> 3) & 1);                           \
    const uint32_t sxor = (uint32_t)(lane & 7);

// ---------------------------------------------------------------------------
// MEGA kernel: [w1t | pool+gate | w2t | gemm1(paired) | gemm2]
// ---------------------------------------------------------------------------
__global__ __launch_bounds__(256, 2) void mega_kernel(
        const float* __restrict__ x,  const float* __restrict__ gw,
        const float* __restrict__ gb, const float* __restrict__ w1,
        const float* __restrict__ b1, const float* __restrict__ w2,
        const float* __restrict__ b2, float* __restrict__ out,
        float* __restrict__ out_logits) {
    extern __shared__ char smem[];
    const int bid = blockIdx.x;
    const int tid = threadIdx.x;

    if (bid < NB_W1) {
        // ---------------- w1 [E][D][H] -> w1t [E][H][D] ----------------
        float (*tile)[65] = (float (*)[65])smem;
        const int e = bid >> 8, cx = bid & 31, cy = (bid >> 5) & 7;
        transpose64(w1 + (size_t)e * D_ * H_, g_w1t + (size_t)e * H_ * D_,
                    D_, H_, cy * 64, cx * 64, tile, tid);
        __syncthreads();
        if (tid == 0) {
            __threadfence();
            atomicAdd(&g_w1c[e * 16 + (cx >> 1)], 1u);
        }
        return;
    }
    if (bid < OFF_W2) {
        // ---------------- pool + x->fp16; last block of batch does gate ----
        const int pb = bid - OFF_POOL;
        const int b = pb >> 3, ch = pb & 7;
        const size_t rbase = ((size_t)b * T_ + (size_t)ch * 128) * D_;
        #pragma unroll
        for (int half = 0; half < 2; half++) {
            const int d = tid + half * 256;
            float s = 0.f;
            for (int t = 0; t < 128; t++) {
                float v = x[rbase + (size_t)t * D_ + d];
                s += v;
                g_xh[rbase + (size_t)t * D_ + d] = __float2half_rn(v);
            }
            g_pool[b][ch][d] = s;
        }
        __shared__ int is_last;
        __syncthreads();
        if (tid == 0) {
            __threadfence();
            is_last = (atomicAdd(&g_poolc[b], 1u) == 7u) ? 1 : 0;
        }
        __syncthreads();
        if (is_last) {
            __threadfence();
            float* pooled = (float*)smem;          // 512 floats
            float* logits = pooled + 512;          // 8 floats
            #pragma unroll
            for (int half = 0; half < 2; half++) {
                const int d = tid + half * 256;
                float s = 0.f;
                #pragma unroll
                for (int c = 0; c < 8; c++) s += g_pool[b][c][d];
                pooled[d] = s * (1.0f / (float)T_);
            }
            __syncthreads();
            const int w = tid >> 5, lane = tid & 31;
            if (w < E_) {
                float acc = 0.f;
                for (int j = lane; j < D_; j += 32)
                    acc += pooled[j] * gw[(size_t)j * E_ + w];
                #pragma unroll
                for (int o = 16; o > 0; o >>= 1)
                    acc += __shfl_xor_sync(0xffffffffu, acc, o);
                if (lane == 0) logits[w] = acc + gb[w];
            }
            __syncthreads();
            if (tid == 0) {
                int i0 = 0; float l0 = logits[0];
                #pragma unroll
                for (int e = 1; e < E_; e++) if (logits[e] > l0) { l0 = logits[e]; i0 = e; }
                int i1 = -1; float l1 = -1e30f;
                #pragma unroll
                for (int e = 0; e < E_; e++)
                    if (e != i0 && logits[e] > l1) { l1 = logits[e]; i1 = e; }
                float e1 = expf(l1 - l0);
                float inv = 1.0f / (1.0f + e1);
                g_eidx[b][0] = i0; g_eidx[b][1] = i1;
                g_prob[b][0] = inv; g_prob[b][1] = e1 * inv;
                #pragma unroll
                for (int e = 0; e < E_; e++) out_logits[b * E_ + e] = logits[e];
                __threadfence();
                atomicExch(&g_gatef[b], 1u);
            }
        }
        return;
    }
    if (bid < OFF_G1) {
        // ---------------- w2 [E][H][D] -> w2t [E][D][H] ----------------
        float (*tile)[65] = (float (*)[65])smem;
        const int idx = bid - OFF_W2;
        const int e = idx >> 8, cx = idx & 7, cy = (idx >> 3) & 31;
        transpose64(w2 + (size_t)e * H_ * D_, g_w2t + (size_t)e * D_ * H_,
                    H_, D_, cy * 64, cx * 64, tile, tid);
        __syncthreads();
        if (tid == 0) {
            __threadfence();
            atomicAdd(&g_w2c[e * 4 + (cx >> 1)], 1u);
        }
        return;
    }

    // ======================= GEMM paths =======================
    const uint32_t sm_base = smem_u32(smem);
    const int warp = tid >> 5, lane = tid & 31;
    LANE_OFFS();
    const int g = lane >> 2, t4 = lane & 3;

    if (bid < OFF_G2) {
        // =============== GEMM1 (paired m-tiles) ===============
        const int v = bid - OFF_G1;
        const int xt = v & 15, ypair = (v >> 4) & 3, bz = v >> 6;
        const int b = bz >> 1, slot = bz & 1;
        const int n0 = xt * BN;

        if (tid == 0) spin_ge(&g_gatef[b], 1u);
        __syncthreads();
        const int e = g_eidx[b][slot];
        const float p = g_prob[b][slot];
        if (tid == 0) spin_ge(&g_w1c[e * 16 + xt], 16u);
        __syncthreads();

        const __half* Bg = g_w1t + ((size_t)e * H_ + n0) * D_;
        const float* brow = b1 + (size_t)e * H_ + n0;

        #pragma unroll 1
        for (int hm = 0; hm < 2; hm++) {
            const int yt = ypair * 2 + hm;
            const int m0 = yt * BM;
            const __half* Ag = g_xh + ((size_t)b * T_ + m0) * D_;

            float acc[4][4][4];
            #pragma unroll
            for (int i = 0; i < 4; i++)
                #pragma unroll
                for (int j = 0; j < 4; j++)
                    #pragma unroll
                    for (int r = 0; r < 4; r++) acc[i][j][r] = 0.f;

            #define A1(r, c) (Ag + (size_t)(r) * D_ + kk * BK + (c) * 8)
            #define B1(r, c) (Bg + (size_t)(r) * D_ + kk * BK + (c) * 8)
            GEMM_PIPELINE(D_ / BK, A1, B1);      // 8 k-tiles
            #undef A1
            #undef B1

            __half* Hb = g_h + ((size_t)b * T_ + m0) * (2 * H_)
                             + (size_t)slot * H_ + n0;
            #pragma unroll
            for (int mt = 0; mt < 4; mt++) {
                #pragma unroll
                for (int nt = 0; nt < 4; nt++) {
                    #pragma unroll
                    for (int half = 0; half < 2; half++) {
                        const int row = wm + mt * 16 + g + half * 8;
                        const int col = wn + nt * 8 + t4 * 2;
                        float v0 = acc[mt][nt][half * 2 + 0] + brow[col];
                        float v1 = acc[mt][nt][half * 2 + 1] + brow[col + 1];
                        v0 = p * v0 * (1.0f / (1.0f + __expf(-v0)));
                        v1 = p * v1 * (1.0f / (1.0f + __expf(-v1)));
                        *(__half2*)&Hb[(size_t)row * (2 * H_) + col] =
                            __floats2half2_rn(v0, v1);
                    }
                }
            }
            __syncthreads();
            if (tid == 0) {
                __threadfence();
                atomicAdd(&g_cnt[b][yt], 1u);
            }
        }
    } else {
        // =============== GEMM2 ===============
        const int r2 = bid - OFF_G2;
        const int xt = r2 & 3, yt = (r2 >> 2) & 7, b = r2 >> 5;
        const int m0 = yt * BM, n0 = xt * BN;

        if (tid == 0) spin_ge(&g_cnt[b][yt], 32u);
        __syncthreads();
        const int e0 = g_eidx[b][0], e1 = g_eidx[b][1];
        const float p0 = g_prob[b][0], p1 = g_prob[b][1];
        if (tid == 0) {
            spin_ge(&g_w2c[e0 * 4 + xt], 64u);
            spin_ge(&g_w2c[e1 * 4 + xt], 64u);
        }
        __syncthreads();

        const __half* Ag  = g_h + ((size_t)b * T_ + m0) * (2 * H_);
        const __half* Bg0 = g_w2t + ((size_t)e0 * D_ + n0) * H_;
        const __half* Bg1 = g_w2t + ((size_t)e1 * D_ + n0) * H_;

        float acc[4][4][4];
        #pragma unroll
        for (int i = 0; i < 4; i++)
            #pragma unroll
            for (int j = 0; j < 4; j++)
                #pragma unroll
                for (int r = 0; r < 4; r++) acc[i][j][r] = 0.f;

        #define A2(r, c) (Ag + (size_t)(r) * (2 * H_) + kk * BK + (c) * 8)
        #define B2(r, c) ((kk < 32 ? Bg0 : Bg1) + (size_t)(r) * H_ + (kk & 31) * BK + (c) * 8)
        GEMM_PIPELINE((2 * H_) / BK, A2, B2);    // 64 k-tiles
        #undef A2
        #undef B2

        const float* b2r0 = b2 + (size_t)e0 * D_ + n0;
        const float* b2r1 = b2 + (size_t)e1 * D_ + n0;
        const float* xb = x   + ((size_t)b * T_ + m0) * D_ + n0;
        float*       ob = out + ((size_t)b * T_ + m0) * D_ + n0;
        #pragma unroll
        for (int mt = 0; mt < 4; mt++) {
            #pragma unroll
            for (int nt = 0; nt < 4; nt++) {
                #pragma unroll
                for (int half = 0; half < 2; half++) {
                    const int row = wm + mt * 16 + g + half * 8;
                    const int col = wn + nt * 8 + t4 * 2;
                    const float bias0 = p0 * b2r0[col]     + p1 * b2r1[col];
                    const float bias1 = p0 * b2r0[col + 1] + p1 * b2r1[col + 1];
                    const float2 xv = *(const float2*)&xb[(size_t)row * D_ + col];
                    float v0 = acc[mt][nt][half * 2 + 0] + bias0 + xv.x;
                    float v1 = acc[mt][nt][half * 2 + 1] + bias1 + xv.y;
                    *(float2*)&ob[(size_t)row * D_ + col] = make_float2(v0, v1);
                }
            }
        }
    }
}

// ---------------------------------------------------------------------------
extern "C" void kernel_launch(void* const* d_in, const int* in_sizes, int n_in,
                              void* d_out, int out_size) {
    const float* x  = (const float*)d_in[0];
    const float* gw = (const float*)d_in[1];
    const float* gb = (const float*)d_in[2];
    const float* w1 = (const float*)d_in[3];
    const float* b1 = (const float*)d_in[4];
    const float* w2 = (const float*)d_in[5];
    const float* b2 = (const float*)d_in[6];

    float* out = (float*)d_out;
    float* out_logits = out + (size_t)B_ * T_ * D_;

    cudaFuncSetAttribute(mega_kernel, cudaFuncAttributeMaxDynamicSharedMemorySize, SMEMSZ);

    reset_kernel<<<1, 512>>>();
    mega_kernel<<<NB_ALL, 256, SMEMSZ>>>(x, gw, gb, w1, b1, w2, b2, out, out_logits);
}

// round 10
// speedup vs baseline: 1.9078x; 1.9078x over previous
#include <cuda_runtime.h>
#include <cuda_fp16.h>
#include <math.h>
#include <stdint.h>

#define B_ 32
#define T_ 1024
#define D_ 512
#define H_ 2048
#define E_ 8

#define BM 128
#define BN 128
#define BK 64                    // halves per k-tile (4 x k16 mma steps), 128B rows
#define STAGES 3

#define A_BYTES (BM * 128)                    // 16384
#define B_BYTES (BN * 128)                    // 16384
#define STAGE_BYTES (A_BYTES + B_BYTES)       // 32768
#define SMEMSZ (STAGES * STAGE_BYTES)         // 98304

// gemm_fused bid layout: [gemm1 | w2 transpose | gemm2]
#define NB_G1   (16 * 8 * 64)                 // 8192 gemm1 blocks
#define NB_W2T  2048                          // w2 transpose blocks
#define NB_G2   (4 * 8 * 32)                  // 1024 gemm2 blocks
#define OFF_W2T (NB_G1)
#define OFF_G2  (NB_G1 + NB_W2T)
#define NB_ALL  (OFF_G2 + NB_G2)

// ---------------------------------------------------------------------------
// scratch (device globals — no allocation allowed)
// ---------------------------------------------------------------------------
__device__ int      g_eidx[B_][2];
__device__ float    g_prob[B_][2];
__device__ float    g_pool[B_][8][D_];
__device__ unsigned g_cnt[B_][8];                    // gemm1->gemm2 readiness (32)
__device__ unsigned g_w2c[E_ * 4];                   // w2t slice readiness (target 64)
__device__ unsigned g_prep = 0;                      // pool-block completion counter
__device__ __half   g_xh[(size_t)B_ * T_ * D_];      // fp16 x
__device__ __half   g_w1t[(size_t)E_ * H_ * D_];     // w1^T [E][H][D] fp16
__device__ __half   g_w2t[(size_t)E_ * D_ * H_];     // w2^T [E][D][H] fp16
__device__ __half   g_h[(size_t)B_ * T_ * (2 * H_)]; // p*silu(x@w1+b1) fp16

// ---------------------------------------------------------------------------
// helpers
// ---------------------------------------------------------------------------
__device__ __forceinline__ uint32_t smem_u32(const void* p) {
    uint32_t a;
    asm("{ .reg .u64 t; cvta.to.shared.u64 t, %1; cvt.u32.u64 %0, t; }" : "=r"(a) : "l"(p));
    return a;
}
__device__ __forceinline__ void cp16(uint32_t dst, const void* src) {
    asm volatile("cp.async.cg.shared.global [%0], [%1], 16;" :: "r"(dst), "l"(src));
}
__device__ __forceinline__ void cp_commit() {
    asm volatile("cp.async.commit_group;" ::: "memory");
}
template <int N>
__device__ __forceinline__ void cp_wait() {
    asm volatile("cp.async.wait_group %0;" :: "n"(N) : "memory");
}
__device__ __forceinline__ void ldsm_x4(unsigned& r0, unsigned& r1, unsigned& r2,
                                        unsigned& r3, uint32_t addr) {
    asm volatile("ldmatrix.sync.aligned.m8n8.x4.shared.b16 {%0,%1,%2,%3}, [%4];"
        : "=r"(r0), "=r"(r1), "=r"(r2), "=r"(r3) : "r"(addr));
}
__device__ __forceinline__ void ldsm_x2(unsigned& r0, unsigned& r1, uint32_t addr) {
    asm volatile("ldmatrix.sync.aligned.m8n8.x2.shared.b16 {%0,%1}, [%2];"
        : "=r"(r0), "=r"(r1) : "r"(addr));
}
__device__ __forceinline__ void mma_f16(float* d, const unsigned* a, const unsigned* b) {
    asm volatile(
        "mma.sync.aligned.m16n8k16.row.col.f32.f16.f16.f32 "
        "{%0,%1,%2,%3}, {%4,%5,%6,%7}, {%8,%9}, {%0,%1,%2,%3};\n"
        : "+f"(d[0]), "+f"(d[1]), "+f"(d[2]), "+f"(d[3])
        : "r"(a[0]), "r"(a[1]), "r"(a[2]), "r"(a[3]), "r"(b[0]), "r"(b[1]));
}
__device__ __forceinline__ void spin_ge(const unsigned* p, unsigned target) {
    unsigned v;
    do {
        asm volatile("ld.global.acquire.gpu.u32 %0, [%1];" : "=r"(v) : "l"(p) : "memory");
        if (v < target) __nanosleep(128);
    } while (v < target);
}

// ---------------------------------------------------------------------------
// prep kernel: 2304 blocks x 512 threads
//   [0,256)     pool partials + fp16 x + counter resets; last block does gate
//   [256,2304)  w1 [E][D][H] -> w1t [E][H][D] fp16  (64x64 tiles)
// ---------------------------------------------------------------------------
__device__ __forceinline__ void transpose64_512(const float* __restrict__ S,
                                                __half* __restrict__ Dp,
                                                int R, int C, int r0, int c0,
                                                float (*tile)[65], int tid) {
    const int tx = tid & 63, ty = tid >> 6;     // ty 0..7
    #pragma unroll
    for (int i = 0; i < 8; i++) {
        const int row = ty + i * 8;
        tile[row][tx] = S[(size_t)(r0 + row) * C + c0 + tx];
    }
    __syncthreads();
    #pragma unroll
    for (int i = 0; i < 8; i++) {
        const int row = ty + i * 8;
        Dp[(size_t)(c0 + row) * R + r0 + tx] = __float2half_rn(tile[tx][row]);
    }
}

__global__ __launch_bounds__(512) void prep_kernel(const float* __restrict__ x,
                                                   const float* __restrict__ w1,
                                                   const float* __restrict__ gw,
                                                   const float* __restrict__ gb,
                                                   float* __restrict__ out_logits) {
    __shared__ float tile[64][65];
    __shared__ int   is_last;
    const int bid = blockIdx.x;
    const int tid = threadIdx.x;

    if (bid < 256) {
        // -------- pool + convert (+ counter resets) --------
        const int b = bid >> 3, ch = bid & 7;
        if (tid == 0) g_cnt[b][ch] = 0u;               // reset fusion counters
        if (bid == 0 && tid < E_ * 4) g_w2c[tid] = 0u; // reset w2t counters
        const int d = tid;
        const size_t base = ((size_t)b * T_ + (size_t)ch * 128) * D_ + d;
        float s = 0.f;
        for (int t = 0; t < 128; t++) {
            float v = x[base + (size_t)t * D_];
            s += v;
            g_xh[base + (size_t)t * D_] = __float2half_rn(v);
        }
        g_pool[b][ch][d] = s;
        __syncthreads();
        if (tid == 0) {
            __threadfence();
            is_last = (atomicAdd(&g_prep, 1u) == 255u) ? 1 : 0;
        }
        __syncthreads();
        if (is_last) {
            __threadfence();
            // -------- gate: 16 threads per batch --------
            const int bb = tid >> 4, l16 = tid & 15;
            float lg[E_];
            if (bb < B_) {
                #pragma unroll
                for (int e = 0; e < E_; e++) lg[e] = 0.f;
                for (int j = l16; j < D_; j += 16) {
                    float pv = 0.f;
                    #pragma unroll
                    for (int c = 0; c < 8; c++) pv += g_pool[bb][c][j];
                    pv *= (1.0f / (float)T_);
                    #pragma unroll
                    for (int e = 0; e < E_; e++) lg[e] += pv * gw[(size_t)j * E_ + e];
                }
                #pragma unroll
                for (int e = 0; e < E_; e++) {
                    #pragma unroll
                    for (int o = 8; o > 0; o >>= 1)
                        lg[e] += __shfl_xor_sync(0xffffffffu, lg[e], o);
                }
                if (l16 == 0) {
                    float lf[E_];
                    #pragma unroll
                    for (int e = 0; e < E_; e++) lf[e] = lg[e] + gb[e];
                    int i0 = 0; float l0 = lf[0];
                    #pragma unroll
                    for (int e = 1; e < E_; e++) if (lf[e] > l0) { l0 = lf[e]; i0 = e; }
                    int i1 = -1; float l1 = -1e30f;
                    #pragma unroll
                    for (int e = 0; e < E_; e++)
                        if (e != i0 && lf[e] > l1) { l1 = lf[e]; i1 = e; }
                    float e1 = expf(l1 - l0);
                    float inv = 1.0f / (1.0f + e1);
                    g_eidx[bb][0] = i0; g_eidx[bb][1] = i1;
                    g_prob[bb][0] = inv; g_prob[bb][1] = e1 * inv;
                    #pragma unroll
                    for (int e = 0; e < E_; e++) out_logits[bb * E_ + e] = lf[e];
                }
            }
            __syncthreads();
            if (tid == 0) g_prep = 0u;            // self-reset for graph replay
        }
    } else {
        // -------- w1 transpose: [E][D][H] -> [E][H][D] --------
        const int idx = bid - 256;
        const int cx = idx & 31, cy = (idx >> 5) & 7, e = idx >> 8;
        transpose64_512(w1 + (size_t)e * D_ * H_, g_w1t + (size_t)e * H_ * D_,
                        D_, H_, cy * 64, cx * 64, tile, tid);
    }
}

// ---------------------------------------------------------------------------
// GEMM core: 256 threads, 8 warps 2(m)x4(n), warp tile 64x32, fp16 m16n8k16
// Tiles: 128 rows x 128B (64 halves), XOR-swizzled: chunk_phys = chunk ^ (row&7)
// ---------------------------------------------------------------------------

#define ISSUE_STAGE(slot, A_SRC, B_SRC) do {                                   \
    const uint32_t _as = sm_base + (slot) * STAGE_BYTES;                       \
    const uint32_t _bs = _as + A_BYTES;                                        \
    _Pragma("unroll")                                                          \
    for (int _i = 0; _i < 4; _i++) {                                           \
        const int _c = _i * 256 + tid;                                         \
        const int _r = _c >> 3, _lc = _c & 7;                                  \
        cp16(_as + _r * 128 + ((_lc ^ (_r & 7)) << 4), (A_SRC(_r, _lc)));      \
    }                                                                          \
    _Pragma("unroll")                                                          \
    for (int _i = 0; _i < 4; _i++) {                                           \
        const int _c = _i * 256 + tid;                                         \
        const int _r = _c >> 3, _lc = _c & 7;                                  \
        cp16(_bs + _r * 128 + ((_lc ^ (_r & 7)) << 4), (B_SRC(_r, _lc)));      \
    }                                                                          \
} while (0)

#define COMPUTE_STAGE(slot) do {                                               \
    const uint32_t _ab = sm_base + (slot) * STAGE_BYTES;                       \
    const uint32_t _bb = _ab + A_BYTES;                                        \
    _Pragma("unroll")                                                          \
    for (int ks = 0; ks < 4; ks++) {                                           \
        unsigned af[4][4], bf[4][2];                                           \
        _Pragma("unroll")                                                      \
        for (int mt = 0; mt < 4; mt++)                                         \
            ldsm_x4(af[mt][0], af[mt][1], af[mt][2], af[mt][3],                \
                    _ab + arow_off + mt * 2048 + (((2 * ks + ac) ^ sxor) << 4)); \
        _Pragma("unroll")                                                      \
        for (int nt = 0; nt < 4; nt++)                                         \
            ldsm_x2(bf[nt][0], bf[nt][1],                                      \
                    _bb + brow_off + nt * 1024 + (((2 * ks + bc) ^ sxor) << 4)); \
        _Pragma("unroll")                                                      \
        for (int mt = 0; mt < 4; mt++)                                         \
            _Pragma("unroll")                                                  \
            for (int nt = 0; nt < 4; nt++)                                     \
                mma_f16(acc[mt][nt], af[mt], bf[nt]);                          \
    }                                                                          \
} while (0)

#define GEMM_PIPELINE(NK, A_SRC, B_SRC) do {                                   \
    _Pragma("unroll")                                                          \
    for (int s = 0; s < STAGES - 1; s++) {                                     \
        const int kk = s;                                                      \
        ISSUE_STAGE(s, A_SRC, B_SRC);                                          \
        cp_commit();                                                           \
    }                                                                          \
    for (int kt = 0; kt < (NK); kt++) {                                        \
        cp_wait<STAGES - 2>();                                                 \
        __syncthreads();                                                       \
        const int pf = kt + STAGES - 1;                                        \
        if (pf < (NK)) {                                                       \
            const int kk = pf;                                                 \
            ISSUE_STAGE(pf % STAGES, A_SRC, B_SRC);                            \
        }                                                                      \
        cp_commit();                                                           \
        COMPUTE_STAGE(kt % STAGES);                                            \
    }                                                                          \
} while (0)

#define LANE_OFFS()                                                            \
    const int wm = (warp & 1) * 64;                                            \
    const int wn = (warp >> 1) * 32;                                           \
    const uint32_t arow_off = (uint32_t)(wm + (lane & 15)) * 128;              \
    const uint32_t ac = (uint32_t)(lane >> 4);                                 \
    const uint32_t brow_off = (uint32_t)(wn + (lane & 7)) * 128;               \
    const uint32_t bc = (uint32_t)((lane >> 3) & 1);                           \
    const uint32_t sxor = (uint32_t)(lane & 7);

// ---------------------------------------------------------------------------
// fused GEMM kernel: [gemm1 | w2 transpose | gemm2]
// ---------------------------------------------------------------------------
__global__ __launch_bounds__(256, 2) void gemm_fused(const float* __restrict__ b1,
                                                     const float* __restrict__ x,
                                                     const float* __restrict__ w2,
                                                     const float* __restrict__ b2,
                                                     float* __restrict__ out) {
    extern __shared__ char smem[];
    const int bid = blockIdx.x;
    const int tid  = threadIdx.x;

    if (bid >= OFF_W2T && bid < OFF_G2) {
        // -------- w2 transpose: [E][H][D] -> [E][D][H] (256 threads) --------
        float (*tile)[65] = (float (*)[65])smem;
        const int idx = bid - OFF_W2T;
        const int e = idx >> 8, cx = idx & 7, cy = (idx >> 3) & 31;
        const float* S = w2 + (size_t)e * H_ * D_;
        __half* Dp = g_w2t + (size_t)e * D_ * H_;
        const int r0 = cy * 64, c0 = cx * 64;
        const int tx = tid & 63, ty = tid >> 6;     // ty 0..3
        #pragma unroll
        for (int i = 0; i < 16; i++) {
            const int row = ty + i * 4;
            tile[row][tx] = S[(size_t)(r0 + row) * D_ + c0 + tx];
        }
        __syncthreads();
        #pragma unroll
        for (int i = 0; i < 16; i++) {
            const int row = ty + i * 4;
            Dp[(size_t)(c0 + row) * H_ + r0 + tx] = __float2half_rn(tile[tx][row]);
        }
        __syncthreads();
        if (tid == 0) {
            __threadfence();
            atomicAdd(&g_w2c[e * 4 + (cx >> 1)], 1u);
        }
        return;
    }

    const uint32_t sm_base = smem_u32(smem);
    const int warp = tid >> 5, lane = tid & 31;
    LANE_OFFS();
    const int g = lane >> 2, t4 = lane & 3;

    float acc[4][4][4];
    #pragma unroll
    for (int i = 0; i < 4; i++)
        #pragma unroll
        for (int j = 0; j < 4; j++)
            #pragma unroll
            for (int r = 0; r < 4; r++) acc[i][j][r] = 0.f;

    if (bid < NB_G1) {
        // =============== GEMM1 ===============
        const int xt = bid & 15, yt = (bid >> 4) & 7, bz = bid >> 7;
        const int b = bz >> 1, slot = bz & 1;
        const int e = g_eidx[b][slot];
        const float p = g_prob[b][slot];
        const int m0 = yt * BM, n0 = xt * BN;

        const __half* Ag = g_xh  + ((size_t)b * T_ + m0) * D_;
        const __half* Bg = g_w1t + ((size_t)e * H_ + n0) * D_;

        #define A1(r, c) (Ag + (size_t)(r) * D_ + kk * BK + (c) * 8)
        #define B1(r, c) (Bg + (size_t)(r) * D_ + kk * BK + (c) * 8)
        GEMM_PIPELINE(D_ / BK, A1, B1);      // 8 k-tiles
        #undef A1
        #undef B1

        const float* brow = b1 + (size_t)e * H_ + n0;
        __half* Hb = g_h + ((size_t)b * T_ + m0) * (2 * H_) + (size_t)slot * H_ + n0;
        #pragma unroll
        for (int mt = 0; mt < 4; mt++) {
            #pragma unroll
            for (int nt = 0; nt < 4; nt++) {
                #pragma unroll
                for (int half = 0; half < 2; half++) {
                    const int row = wm + mt * 16 + g + half * 8;
                    const int col = wn + nt * 8 + t4 * 2;
                    float v0 = acc[mt][nt][half * 2 + 0] + brow[col];
                    float v1 = acc[mt][nt][half * 2 + 1] + brow[col + 1];
                    v0 = p * v0 * (1.0f / (1.0f + __expf(-v0)));
                    v1 = p * v1 * (1.0f / (1.0f + __expf(-v1)));
                    *(__half2*)&Hb[(size_t)row * (2 * H_) + col] =
                        __floats2half2_rn(v0, v1);
                }
            }
        }
        // release
        __syncthreads();
        if (tid == 0) {
            __threadfence();
            atomicAdd(&g_cnt[b][yt], 1u);
        }
    } else {
        // =============== GEMM2 ===============
        const int r2 = bid - OFF_G2;
        const int xt = r2 & 3, yt = (r2 >> 2) & 7, b = r2 >> 5;
        const int m0 = yt * BM, n0 = xt * BN;

        // acquire: 32 gemm1 producers + the w2t slices for both experts
        if (tid == 0) spin_ge(&g_cnt[b][yt], 32u);
        __syncthreads();
        const int e0 = g_eidx[b][0], e1 = g_eidx[b][1];
        const float p0 = g_prob[b][0], p1 = g_prob[b][1];
        if (tid == 0) {
            spin_ge(&g_w2c[e0 * 4 + xt], 64u);
            spin_ge(&g_w2c[e1 * 4 + xt], 64u);
        }
        __syncthreads();

        const __half* Ag  = g_h + ((size_t)b * T_ + m0) * (2 * H_);
        const __half* Bg0 = g_w2t + ((size_t)e0 * D_ + n0) * H_;
        const __half* Bg1 = g_w2t + ((size_t)e1 * D_ + n0) * H_;

        #define A2(r, c) (Ag + (size_t)(r) * (2 * H_) + kk * BK + (c) * 8)
        #define B2(r, c) ((kk < 32 ? Bg0 : Bg1) + (size_t)(r) * H_ + (kk & 31) * BK + (c) * 8)
        GEMM_PIPELINE((2 * H_) / BK, A2, B2);    // 64 k-tiles
        #undef A2
        #undef B2

        const float* b2r0 = b2 + (size_t)e0 * D_ + n0;
        const float* b2r1 = b2 + (size_t)e1 * D_ + n0;
        const float* xb = x   + ((size_t)b * T_ + m0) * D_ + n0;
        float*       ob = out + ((size_t)b * T_ + m0) * D_ + n0;
        #pragma unroll
        for (int mt = 0; mt < 4; mt++) {
            #pragma unroll
            for (int nt = 0; nt < 4; nt++) {
                #pragma unroll
                for (int half = 0; half < 2; half++) {
                    const int row = wm + mt * 16 + g + half * 8;
                    const int col = wn + nt * 8 + t4 * 2;
                    const float bias0 = p0 * b2r0[col]     + p1 * b2r1[col];
                    const float bias1 = p0 * b2r0[col + 1] + p1 * b2r1[col + 1];
                    const float2 xv = *(const float2*)&xb[(size_t)row * D_ + col];
                    float v0 = acc[mt][nt][half * 2 + 0] + bias0 + xv.x;
                    float v1 = acc[mt][nt][half * 2 + 1] + bias1 + xv.y;
                    *(float2*)&ob[(size_t)row * D_ + col] = make_float2(v0, v1);
                }
            }
        }
    }
}

// ---------------------------------------------------------------------------
extern "C" void kernel_launch(void* const* d_in, const int* in_sizes, int n_in,
                              void* d_out, int out_size) {
    const float* x  = (const float*)d_in[0];
    const float* gw = (const float*)d_in[1];
    const float* gb = (const float*)d_in[2];
    const float* w1 = (const float*)d_in[3];
    const float* b1 = (const float*)d_in[4];
    const float* w2 = (const float*)d_in[5];
    const float* b2 = (const float*)d_in[6];

    float* out = (float*)d_out;
    float* out_logits = out + (size_t)B_ * T_ * D_;

    cudaFuncSetAttribute(gemm_fused, cudaFuncAttributeMaxDynamicSharedMemorySize, SMEMSZ);

    prep_kernel<<<256 + 2048, 512>>>(x, w1, gw, gb, out_logits);
    gemm_fused<<<NB_ALL, 256, SMEMSZ>>>(b1, x, w2, b2, out);
}